// round 1
// baseline (speedup 1.0000x reference)
#include <cuda_runtime.h>

// ---------------- f32x2 packed-math helpers (Blackwell FFMA2 path) ----------------

__device__ __forceinline__ unsigned long long ffma2(unsigned long long a,
                                                    unsigned long long b,
                                                    unsigned long long c) {
    unsigned long long d;
    asm("fma.rn.f32x2 %0, %1, %2, %3;" : "=l"(d) : "l"(a), "l"(b), "l"(c));
    return d;
}

__device__ __forceinline__ unsigned long long pk2(float x, float y) {
    unsigned long long r;
    asm("mov.b64 %0, {%1, %2};" : "=l"(r) : "f"(x), "f"(y));
    return r;
}

__device__ __forceinline__ void unpk2(unsigned long long v, float& x, float& y) {
    asm("mov.b64 {%0, %1}, %2;" : "=f"(x), "=f"(y) : "l"(v));
}

// ---------------- shared-memory weight cache (masks + interleave baked) ----------------

struct __align__(16) Smem {
    float W1[4 * 64];     // enc layer1, row-major (in, out)
    float B1[64];
    float W2[64 * 32];
    float B2[32];
    float W3[32 * 8];
    float B3[8];
    float Pj[16];         // proj: interleaved {w[i][0], w[i][1]} pairs
    float Pc[8];          // proj: w[i][2]
    float Fh[10 * 64];    // flow hidden: [l][input(2)][32], input-1 row mask-baked
    float Fbh[10 * 32];
    float Fo[10 * 128];   // flow out: [l][k][4] = {wmu1*m, wa1*m, wmu2, wa2}
    float Fb[10 * 6 + 4]; // [l] = {bmu0, exp(-tanh(ba0)), bmu1, ba1, bmu2, ba2}
    float Pb[4];          // proj bias (3 used)
};

__global__ __launch_bounds__(128)
void gsi_kernel(const float* __restrict__ states,
                const float* __restrict__ enc_w1, const float* __restrict__ enc_b1,
                const float* __restrict__ enc_w2, const float* __restrict__ enc_b2,
                const float* __restrict__ enc_w3, const float* __restrict__ enc_b3,
                const float* __restrict__ proj_w, const float* __restrict__ proj_b,
                const float* __restrict__ flow_wh, const float* __restrict__ flow_bh,
                const float* __restrict__ flow_wmu, const float* __restrict__ flow_bmu,
                const float* __restrict__ flow_wa, const float* __restrict__ flow_ba,
                float* __restrict__ out, int B) {
    __shared__ Smem sm;
    const int tid = threadIdx.x;

    // ---- cooperative weight load + mask/interleave bake ----
    for (int i = tid; i < 4 * 64; i += 128)  sm.W1[i] = enc_w1[i];
    for (int i = tid; i < 64;     i += 128)  sm.B1[i] = enc_b1[i];
    for (int i = tid; i < 64 * 32; i += 128) sm.W2[i] = enc_w2[i];
    for (int i = tid; i < 32;     i += 128)  sm.B2[i] = enc_b2[i];
    for (int i = tid; i < 32 * 8; i += 128)  sm.W3[i] = enc_w3[i];
    for (int i = tid; i < 8;      i += 128)  sm.B3[i] = enc_b3[i];
    if (tid < 8) {
        sm.Pj[2 * tid]     = proj_w[tid * 3 + 0];
        sm.Pj[2 * tid + 1] = proj_w[tid * 3 + 1];
        sm.Pc[tid]         = proj_w[tid * 3 + 2];
    }
    if (tid < 3) sm.Pb[tid] = proj_b[tid];
    if (tid == 3) sm.Pb[3] = 0.f;
    // flow hidden weights: m_h[0][j]=1 all j; m_h[1][j]=1 iff j odd; m_h[2][:]=0 (dropped)
    for (int i = tid; i < 10 * 32; i += 128) {
        int l = i >> 5, j = i & 31;
        sm.Fh[l * 64 + j]      = flow_wh[l * 96 + j];
        sm.Fh[l * 64 + 32 + j] = (j & 1) ? flow_wh[l * 96 + 32 + j] : 0.f;
        sm.Fbh[i] = flow_bh[i];
    }
    // flow output weights: m_o[k][1]=1 iff k even; m_o[k][2]=1; m_o[k][0]=0 (out0 = bias)
    for (int i = tid; i < 10 * 32; i += 128) {
        int l = i >> 5, k = i & 31;
        int base = l * 96 + k * 3;
        float m1 = (k & 1) ? 0.f : 1.f;
        sm.Fo[i * 4 + 0] = flow_wmu[base + 1] * m1;
        sm.Fo[i * 4 + 1] = flow_wa[base + 1] * m1;
        sm.Fo[i * 4 + 2] = flow_wmu[base + 2];
        sm.Fo[i * 4 + 3] = flow_wa[base + 2];
    }
    if (tid < 10) {
        int l = tid;
        sm.Fb[l * 6 + 0] = flow_bmu[l * 3 + 0];
        sm.Fb[l * 6 + 1] = expf(-tanhf(flow_ba[l * 3 + 0]));  // accurate, once
        sm.Fb[l * 6 + 2] = flow_bmu[l * 3 + 1];
        sm.Fb[l * 6 + 3] = flow_ba[l * 3 + 1];
        sm.Fb[l * 6 + 4] = flow_bmu[l * 3 + 2];
        sm.Fb[l * 6 + 5] = flow_ba[l * 3 + 2];
    }
    __syncthreads();

    const int r = blockIdx.x * 128 + tid;
    if (r >= B) return;

    const float4 s4 = reinterpret_cast<const float4*>(states)[r];

    // ---- encoder layer 1: 4 -> 64, outputs packed in pairs ----
    unsigned long long h1[32];
    {
        const ulonglong2* pb = reinterpret_cast<const ulonglong2*>(sm.B1);
#pragma unroll
        for (int p = 0; p < 16; p++) { ulonglong2 v = pb[p]; h1[2 * p] = v.x; h1[2 * p + 1] = v.y; }
        float xin[4] = {s4.x, s4.y, s4.z, s4.w};
#pragma unroll
        for (int i = 0; i < 4; i++) {
            unsigned long long xb = pk2(xin[i], xin[i]);
            const ulonglong2* w = reinterpret_cast<const ulonglong2*>(sm.W1 + i * 64);
#pragma unroll
            for (int p = 0; p < 16; p++) {
                ulonglong2 v = w[p];
                h1[2 * p]     = ffma2(xb, v.x, h1[2 * p]);
                h1[2 * p + 1] = ffma2(xb, v.y, h1[2 * p + 1]);
            }
        }
    }

    // ---- encoder layer 2: 64 -> 32 (relu fused into unpack/broadcast) ----
    unsigned long long h2[16];
    {
        const ulonglong2* pb = reinterpret_cast<const ulonglong2*>(sm.B2);
#pragma unroll
        for (int p = 0; p < 8; p++) { ulonglong2 v = pb[p]; h2[2 * p] = v.x; h2[2 * p + 1] = v.y; }
#pragma unroll 8
        for (int j = 0; j < 32; j++) {
            float a, b; unpk2(h1[j], a, b);
            a = fmaxf(a, 0.f); b = fmaxf(b, 0.f);
            unsigned long long ab = pk2(a, a), bb = pk2(b, b);
            const ulonglong2* wA = reinterpret_cast<const ulonglong2*>(sm.W2 + (2 * j) * 32);
            const ulonglong2* wB = reinterpret_cast<const ulonglong2*>(sm.W2 + (2 * j + 1) * 32);
#pragma unroll
            for (int p = 0; p < 8; p++) {
                ulonglong2 va = wA[p];
                h2[2 * p]     = ffma2(ab, va.x, h2[2 * p]);
                h2[2 * p + 1] = ffma2(ab, va.y, h2[2 * p + 1]);
            }
#pragma unroll
            for (int p = 0; p < 8; p++) {
                ulonglong2 vb = wB[p];
                h2[2 * p]     = ffma2(bb, vb.x, h2[2 * p]);
                h2[2 * p + 1] = ffma2(bb, vb.y, h2[2 * p + 1]);
            }
        }
    }

    // ---- encoder layer 3: 32 -> 8 (no relu on output) ----
    unsigned long long cp[4];
    {
        const ulonglong2* pb = reinterpret_cast<const ulonglong2*>(sm.B3);
        ulonglong2 v0 = pb[0], v1 = pb[1];
        cp[0] = v0.x; cp[1] = v0.y; cp[2] = v1.x; cp[3] = v1.y;
#pragma unroll
        for (int j = 0; j < 16; j++) {
            float a, b; unpk2(h2[j], a, b);
            a = fmaxf(a, 0.f); b = fmaxf(b, 0.f);
            unsigned long long ab = pk2(a, a), bb = pk2(b, b);
            const ulonglong2* wA = reinterpret_cast<const ulonglong2*>(sm.W3 + (2 * j) * 8);
            const ulonglong2* wB = reinterpret_cast<const ulonglong2*>(sm.W3 + (2 * j + 1) * 8);
            ulonglong2 va0 = wA[0], va1 = wA[1];
            cp[0] = ffma2(ab, va0.x, cp[0]); cp[1] = ffma2(ab, va0.y, cp[1]);
            cp[2] = ffma2(ab, va1.x, cp[2]); cp[3] = ffma2(ab, va1.y, cp[3]);
            ulonglong2 vb0 = wB[0], vb1 = wB[1];
            cp[0] = ffma2(bb, vb0.x, cp[0]); cp[1] = ffma2(bb, vb0.y, cp[1]);
            cp[2] = ffma2(bb, vb1.x, cp[2]); cp[3] = ffma2(bb, vb1.y, cp[3]);
        }
    }
    float c[8];
    unpk2(cp[0], c[0], c[1]); unpk2(cp[1], c[2], c[3]);
    unpk2(cp[2], c[4], c[5]); unpk2(cp[3], c[6], c[7]);

    // ---- projection 8 -> 3 ----
    unsigned long long a01 = pk2(sm.Pb[0], sm.Pb[1]);
    float x2 = sm.Pb[2];
#pragma unroll
    for (int i = 0; i < 8; i++) {
        unsigned long long cb = pk2(c[i], c[i]);
        unsigned long long w = reinterpret_cast<const unsigned long long*>(sm.Pj)[i];
        a01 = ffma2(cb, w, a01);
        x2 = fmaf(c[i], sm.Pc[i], x2);
    }
    float x0, x1;
    unpk2(a01, x0, x1);

    // ---- MAF flow: 10 masked affine-AR layers + flip ----
#pragma unroll 1
    for (int l = 0; l < 10; l++) {
        const float* fh  = sm.Fh  + l * 64;
        const float* fbh = sm.Fbh + l * 32;
        const float* fo  = sm.Fo  + l * 128;
        const float* fb  = sm.Fb  + l * 6;

        unsigned long long hh[16];
        const ulonglong2* pbh = reinterpret_cast<const ulonglong2*>(fbh);
#pragma unroll
        for (int p = 0; p < 8; p++) { ulonglong2 v = pbh[p]; hh[2 * p] = v.x; hh[2 * p + 1] = v.y; }
        unsigned long long x0b = pk2(x0, x0), x1b = pk2(x1, x1);
        const ulonglong2* w0 = reinterpret_cast<const ulonglong2*>(fh);
        const ulonglong2* w1 = reinterpret_cast<const ulonglong2*>(fh + 32);
#pragma unroll
        for (int p = 0; p < 8; p++) {
            ulonglong2 v = w0[p];
            hh[2 * p]     = ffma2(x0b, v.x, hh[2 * p]);
            hh[2 * p + 1] = ffma2(x0b, v.y, hh[2 * p + 1]);
        }
#pragma unroll
        for (int p = 0; p < 8; p++) {
            ulonglong2 v = w1[p];
            hh[2 * p]     = ffma2(x1b, v.x, hh[2 * p]);
            hh[2 * p + 1] = ffma2(x1b, v.y, hh[2 * p + 1]);
        }

        // second stage: acc1 = {mu1, alpha1}, acc2 = {mu2, alpha2}
        unsigned long long acc1 = pk2(fb[2], fb[3]);
        unsigned long long acc2 = pk2(fb[4], fb[5]);
#pragma unroll
        for (int j = 0; j < 16; j++) {
            float a, b; unpk2(hh[j], a, b);
            a = fmaxf(a, 0.f); b = fmaxf(b, 0.f);
            unsigned long long ab = pk2(a, a), bb = pk2(b, b);
            const ulonglong2* wk = reinterpret_cast<const ulonglong2*>(fo + (2 * j) * 4);
            ulonglong2 vA = wk[0];
            acc1 = ffma2(ab, vA.x, acc1); acc2 = ffma2(ab, vA.y, acc2);
            ulonglong2 vB = wk[1];
            acc1 = ffma2(bb, vB.x, acc1); acc2 = ffma2(bb, vB.y, acc2);
        }
        float mu1, al1, mu2, al2;
        unpk2(acc1, mu1, al1); unpk2(acc2, mu2, al2);
        // tanh(z) = 1 - 2/(exp(2z)+1)  (robust, no cancellation issue at small z)
        float t1 = 1.f - __fdividef(2.f, __expf(2.f * al1) + 1.f);
        float t2 = 1.f - __fdividef(2.f, __expf(2.f * al2) + 1.f);
        float nx0 = (x0 - fb[0]) * fb[1];        // exp(-tanh(ba0)) pre-baked
        float nx1 = (x1 - mu1) * __expf(-t1);
        float nx2 = (x2 - mu2) * __expf(-t2);
        // flip
        x0 = nx2; x1 = nx1; x2 = nx0;
    }

    // ---- squash + HSV ----
    float u0 = __fdividef(1.f, 1.f + __expf(-x0));
    float u1 = __fdividef(1.f, 1.f + __expf(-x1));
    float u2 = __fdividef(1.f, 1.f + __expf(-x2));
    out[3 * r + 0] = 6.2831853071795864769f * u0;
    out[3 * r + 1] = u1;
    out[3 * r + 2] = u2;
}

extern "C" void kernel_launch(void* const* d_in, const int* in_sizes, int n_in,
                              void* d_out, int out_size) {
    (void)n_in; (void)out_size;
    const float* states   = (const float*)d_in[0];
    const float* enc_w1   = (const float*)d_in[1];
    const float* enc_b1   = (const float*)d_in[2];
    const float* enc_w2   = (const float*)d_in[3];
    const float* enc_b2   = (const float*)d_in[4];
    const float* enc_w3   = (const float*)d_in[5];
    const float* enc_b3   = (const float*)d_in[6];
    const float* proj_w   = (const float*)d_in[7];
    const float* proj_b   = (const float*)d_in[8];
    const float* flow_wh  = (const float*)d_in[9];
    const float* flow_bh  = (const float*)d_in[10];
    const float* flow_wmu = (const float*)d_in[11];
    const float* flow_bmu = (const float*)d_in[12];
    const float* flow_wa  = (const float*)d_in[13];
    const float* flow_ba  = (const float*)d_in[14];

    const int B = in_sizes[0] / 4;
    const int grid = (B + 127) / 128;
    gsi_kernel<<<grid, 128>>>(states, enc_w1, enc_b1, enc_w2, enc_b2, enc_w3, enc_b3,
                              proj_w, proj_b, flow_wh, flow_bh, flow_wmu, flow_bmu,
                              flow_wa, flow_ba, (float*)d_out, B);
}

// round 2
// speedup vs baseline: 1.6897x; 1.6897x over previous
#include <cuda_runtime.h>

using ull = unsigned long long;

// ---------------- f32x2 packed-math helpers (Blackwell FFMA2 path) ----------------

__device__ __forceinline__ ull ffma2(ull a, ull b, ull c) {
    ull d;
    asm("fma.rn.f32x2 %0, %1, %2, %3;" : "=l"(d) : "l"(a), "l"(b), "l"(c));
    return d;
}
__device__ __forceinline__ ull pk2(float x, float y) {
    ull r;
    asm("mov.b64 %0, {%1, %2};" : "=l"(r) : "f"(x), "f"(y));
    return r;
}
__device__ __forceinline__ void unpk2(ull v, float& x, float& y) {
    asm("mov.b64 {%0, %1}, %2;" : "=f"(x), "=f"(y) : "l"(v));
}

// ---------------- shared-memory weight cache (masks + interleave baked) ----------------

struct __align__(16) Smem {
    float W1[4 * 64];
    float B1[64];
    float W2[64 * 32];
    float B2[32];
    float W3[32 * 8];
    float B3[8];
    float Pj[16];          // proj: interleaved {w[i][0], w[i][1]} pairs
    float Pc[8];           // proj: w[i][2]
    float Fh[10 * 64];     // flow hidden: [l][input(2)][32], input-1 row mask-baked
    float Fbh[10 * 32];
    float FoA[10 * 32];    // per layer 16 pairs: {wmu1[2j], wa1[2j]} (even units only; odd are masked to 0)
    float FoB[10 * 64];    // per layer 32 pairs: {wmu2[k], wa2[k]} (all units)
    float Fb[10 * 6 + 4];  // [l] = {bmu0, exp(-tanh(ba0)), bmu1, ba1, bmu2, ba2}
    float Pb[4];
};

__global__ __launch_bounds__(128)
void gsi_kernel(const float* __restrict__ states,
                const float* __restrict__ enc_w1, const float* __restrict__ enc_b1,
                const float* __restrict__ enc_w2, const float* __restrict__ enc_b2,
                const float* __restrict__ enc_w3, const float* __restrict__ enc_b3,
                const float* __restrict__ proj_w, const float* __restrict__ proj_b,
                const float* __restrict__ flow_wh, const float* __restrict__ flow_bh,
                const float* __restrict__ flow_wmu, const float* __restrict__ flow_bmu,
                const float* __restrict__ flow_wa, const float* __restrict__ flow_ba,
                float* __restrict__ out, int B) {
    __shared__ Smem sm;
    const int tid = threadIdx.x;

    // ---- cooperative weight load + mask/interleave bake ----
    for (int i = tid; i < 4 * 64; i += 128)  sm.W1[i] = enc_w1[i];
    for (int i = tid; i < 64;     i += 128)  sm.B1[i] = enc_b1[i];
    for (int i = tid; i < 64 * 32; i += 128) sm.W2[i] = enc_w2[i];
    for (int i = tid; i < 32;     i += 128)  sm.B2[i] = enc_b2[i];
    for (int i = tid; i < 32 * 8; i += 128)  sm.W3[i] = enc_w3[i];
    for (int i = tid; i < 8;      i += 128)  sm.B3[i] = enc_b3[i];
    if (tid < 8) {
        sm.Pj[2 * tid]     = proj_w[tid * 3 + 0];
        sm.Pj[2 * tid + 1] = proj_w[tid * 3 + 1];
        sm.Pc[tid]         = proj_w[tid * 3 + 2];
    }
    if (tid < 3) sm.Pb[tid] = proj_b[tid];
    if (tid == 3) sm.Pb[3] = 0.f;
    // flow hidden: m_h[0][j]=1 all j; m_h[1][j]=1 iff j odd; m_h[2][:]=0 (dropped)
    for (int i = tid; i < 10 * 32; i += 128) {
        int l = i >> 5, j = i & 31;
        sm.Fh[l * 64 + j]      = flow_wh[l * 96 + j];
        sm.Fh[l * 64 + 32 + j] = (j & 1) ? flow_wh[l * 96 + 32 + j] : 0.f;
        sm.Fbh[i] = flow_bh[i];
    }
    // flow output: m_o[k][1]=1 iff k even; m_o[k][2]=1; m_o[k][0]=0 (out0 = pure bias)
    for (int i = tid; i < 10 * 16; i += 128) {       // FoA: even units only
        int l = i >> 4, j = i & 15;
        int base = l * 96 + (2 * j) * 3;
        sm.FoA[l * 32 + 2 * j]     = flow_wmu[base + 1];
        sm.FoA[l * 32 + 2 * j + 1] = flow_wa[base + 1];
    }
    for (int i = tid; i < 10 * 32; i += 128) {       // FoB: all units
        int l = i >> 5, k = i & 31;
        int base = l * 96 + k * 3;
        sm.FoB[l * 64 + 2 * k]     = flow_wmu[base + 2];
        sm.FoB[l * 64 + 2 * k + 1] = flow_wa[base + 2];
    }
    if (tid < 10) {
        int l = tid;
        sm.Fb[l * 6 + 0] = flow_bmu[l * 3 + 0];
        sm.Fb[l * 6 + 1] = expf(-tanhf(flow_ba[l * 3 + 0]));
        sm.Fb[l * 6 + 2] = flow_bmu[l * 3 + 1];
        sm.Fb[l * 6 + 3] = flow_ba[l * 3 + 1];
        sm.Fb[l * 6 + 4] = flow_bmu[l * 3 + 2];
        sm.Fb[l * 6 + 5] = flow_ba[l * 3 + 2];
    }
    __syncthreads();

    // ---- 2 rows per thread: every weight LDS amortized over both ----
    const int r0 = blockIdx.x * 256 + tid;
    const int r1 = r0 + 128;
    const bool v0 = r0 < B, v1 = r1 < B;
    const float4 sA = v0 ? reinterpret_cast<const float4*>(states)[r0] : make_float4(0.f, 0.f, 0.f, 0.f);
    const float4 sB = v1 ? reinterpret_cast<const float4*>(states)[r1] : make_float4(0.f, 0.f, 0.f, 0.f);

    // ---- fused enc1 (4->64) + enc2 (64->32), chunked 16 hidden units at a time ----
    ull h2A[16], h2B[16];
    {
        const ulonglong2* pb = reinterpret_cast<const ulonglong2*>(sm.B2);
#pragma unroll
        for (int p = 0; p < 8; p++) {
            ulonglong2 v = pb[p];
            h2A[2 * p] = v.x; h2A[2 * p + 1] = v.y;
            h2B[2 * p] = v.x; h2B[2 * p + 1] = v.y;
        }
    }
    ull xpA[4], xpB[4];
    xpA[0] = pk2(sA.x, sA.x); xpA[1] = pk2(sA.y, sA.y); xpA[2] = pk2(sA.z, sA.z); xpA[3] = pk2(sA.w, sA.w);
    xpB[0] = pk2(sB.x, sB.x); xpB[1] = pk2(sB.y, sB.y); xpB[2] = pk2(sB.z, sB.z); xpB[3] = pk2(sB.w, sB.w);

#pragma unroll 1
    for (int c = 0; c < 4; c++) {
        ull h1A[8], h1B[8];
        const ulonglong2* pb1 = reinterpret_cast<const ulonglong2*>(sm.B1 + c * 16);
#pragma unroll
        for (int p = 0; p < 4; p++) {
            ulonglong2 v = pb1[p];
            h1A[2 * p] = v.x; h1A[2 * p + 1] = v.y;
            h1B[2 * p] = v.x; h1B[2 * p + 1] = v.y;
        }
#pragma unroll
        for (int i = 0; i < 4; i++) {
            const ulonglong2* w = reinterpret_cast<const ulonglong2*>(sm.W1 + i * 64 + c * 16);
#pragma unroll
            for (int p = 0; p < 4; p++) {
                ulonglong2 v = w[p];
                h1A[2 * p]     = ffma2(xpA[i], v.x, h1A[2 * p]);
                h1A[2 * p + 1] = ffma2(xpA[i], v.y, h1A[2 * p + 1]);
                h1B[2 * p]     = ffma2(xpB[i], v.x, h1B[2 * p]);
                h1B[2 * p + 1] = ffma2(xpB[i], v.y, h1B[2 * p + 1]);
            }
        }
        // consume this chunk into h2
#pragma unroll
        for (int j = 0; j < 8; j++) {
            float aA, bA, aB, bB;
            unpk2(h1A[j], aA, bA); unpk2(h1B[j], aB, bB);
            aA = fmaxf(aA, 0.f); bA = fmaxf(bA, 0.f);
            aB = fmaxf(aB, 0.f); bB = fmaxf(bB, 0.f);
            ull abA = pk2(aA, aA), bbA = pk2(bA, bA);
            ull abB = pk2(aB, aB), bbB = pk2(bB, bB);
            const int u = c * 16 + 2 * j;
            const ulonglong2* wa = reinterpret_cast<const ulonglong2*>(sm.W2 + u * 32);
            const ulonglong2* wb = reinterpret_cast<const ulonglong2*>(sm.W2 + u * 32 + 32);
#pragma unroll
            for (int p = 0; p < 8; p++) {
                ulonglong2 v = wa[p];
                h2A[2 * p]     = ffma2(abA, v.x, h2A[2 * p]);
                h2A[2 * p + 1] = ffma2(abA, v.y, h2A[2 * p + 1]);
                h2B[2 * p]     = ffma2(abB, v.x, h2B[2 * p]);
                h2B[2 * p + 1] = ffma2(abB, v.y, h2B[2 * p + 1]);
            }
#pragma unroll
            for (int p = 0; p < 8; p++) {
                ulonglong2 v = wb[p];
                h2A[2 * p]     = ffma2(bbA, v.x, h2A[2 * p]);
                h2A[2 * p + 1] = ffma2(bbA, v.y, h2A[2 * p + 1]);
                h2B[2 * p]     = ffma2(bbB, v.x, h2B[2 * p]);
                h2B[2 * p + 1] = ffma2(bbB, v.y, h2B[2 * p + 1]);
            }
        }
    }

    // ---- enc3: 32 -> 8 ----
    ull cpA[4], cpB[4];
    {
        const ulonglong2* pb = reinterpret_cast<const ulonglong2*>(sm.B3);
        ulonglong2 v0b = pb[0], v1b = pb[1];
        cpA[0] = v0b.x; cpA[1] = v0b.y; cpA[2] = v1b.x; cpA[3] = v1b.y;
        cpB[0] = v0b.x; cpB[1] = v0b.y; cpB[2] = v1b.x; cpB[3] = v1b.y;
    }
#pragma unroll
    for (int j = 0; j < 16; j++) {
        float aA, bA, aB, bB;
        unpk2(h2A[j], aA, bA); unpk2(h2B[j], aB, bB);
        aA = fmaxf(aA, 0.f); bA = fmaxf(bA, 0.f);
        aB = fmaxf(aB, 0.f); bB = fmaxf(bB, 0.f);
        ull abA = pk2(aA, aA), bbA = pk2(bA, bA);
        ull abB = pk2(aB, aB), bbB = pk2(bB, bB);
        const ulonglong2* wa = reinterpret_cast<const ulonglong2*>(sm.W3 + (2 * j) * 8);
        const ulonglong2* wb = reinterpret_cast<const ulonglong2*>(sm.W3 + (2 * j + 1) * 8);
        ulonglong2 va0 = wa[0], va1 = wa[1];
        cpA[0] = ffma2(abA, va0.x, cpA[0]); cpA[1] = ffma2(abA, va0.y, cpA[1]);
        cpA[2] = ffma2(abA, va1.x, cpA[2]); cpA[3] = ffma2(abA, va1.y, cpA[3]);
        cpB[0] = ffma2(abB, va0.x, cpB[0]); cpB[1] = ffma2(abB, va0.y, cpB[1]);
        cpB[2] = ffma2(abB, va1.x, cpB[2]); cpB[3] = ffma2(abB, va1.y, cpB[3]);
        ulonglong2 vb0 = wb[0], vb1 = wb[1];
        cpA[0] = ffma2(bbA, vb0.x, cpA[0]); cpA[1] = ffma2(bbA, vb0.y, cpA[1]);
        cpA[2] = ffma2(bbA, vb1.x, cpA[2]); cpA[3] = ffma2(bbA, vb1.y, cpA[3]);
        cpB[0] = ffma2(bbB, vb0.x, cpB[0]); cpB[1] = ffma2(bbB, vb0.y, cpB[1]);
        cpB[2] = ffma2(bbB, vb1.x, cpB[2]); cpB[3] = ffma2(bbB, vb1.y, cpB[3]);
    }
    float cA[8], cB[8];
    unpk2(cpA[0], cA[0], cA[1]); unpk2(cpA[1], cA[2], cA[3]);
    unpk2(cpA[2], cA[4], cA[5]); unpk2(cpA[3], cA[6], cA[7]);
    unpk2(cpB[0], cB[0], cB[1]); unpk2(cpB[1], cB[2], cB[3]);
    unpk2(cpB[2], cB[4], cB[5]); unpk2(cpB[3], cB[6], cB[7]);

    // ---- projection 8 -> 3 ----
    ull a01A = pk2(sm.Pb[0], sm.Pb[1]), a01B = a01A;
    float x2A = sm.Pb[2], x2B = sm.Pb[2];
#pragma unroll
    for (int i = 0; i < 8; i++) {
        ull w = reinterpret_cast<const ull*>(sm.Pj)[i];
        float pc = sm.Pc[i];
        ull cbA = pk2(cA[i], cA[i]);
        a01A = ffma2(cbA, w, a01A);
        x2A = fmaf(cA[i], pc, x2A);
        ull cbB = pk2(cB[i], cB[i]);
        a01B = ffma2(cbB, w, a01B);
        x2B = fmaf(cB[i], pc, x2B);
    }
    float x0A, x1A, x0B, x1B;
    unpk2(a01A, x0A, x1A); unpk2(a01B, x0B, x1B);

    // ---- MAF flow: 10 masked affine-AR layers + flip ----
#pragma unroll 1
    for (int l = 0; l < 10; l++) {
        const float* fh  = sm.Fh  + l * 64;
        const float* fbh = sm.Fbh + l * 32;
        const float* foA = sm.FoA + l * 32;
        const float* foB = sm.FoB + l * 64;
        const float* fb  = sm.Fb  + l * 6;

        ull hhA[16], hhB[16];
        const ulonglong2* pbh = reinterpret_cast<const ulonglong2*>(fbh);
#pragma unroll
        for (int p = 0; p < 8; p++) {
            ulonglong2 v = pbh[p];
            hhA[2 * p] = v.x; hhA[2 * p + 1] = v.y;
            hhB[2 * p] = v.x; hhB[2 * p + 1] = v.y;
        }
        ull x0bA = pk2(x0A, x0A), x1bA = pk2(x1A, x1A);
        ull x0bB = pk2(x0B, x0B), x1bB = pk2(x1B, x1B);
        const ulonglong2* w0 = reinterpret_cast<const ulonglong2*>(fh);
        const ulonglong2* w1 = reinterpret_cast<const ulonglong2*>(fh + 32);
#pragma unroll
        for (int p = 0; p < 8; p++) {
            ulonglong2 v = w0[p];
            hhA[2 * p]     = ffma2(x0bA, v.x, hhA[2 * p]);
            hhA[2 * p + 1] = ffma2(x0bA, v.y, hhA[2 * p + 1]);
            hhB[2 * p]     = ffma2(x0bB, v.x, hhB[2 * p]);
            hhB[2 * p + 1] = ffma2(x0bB, v.y, hhB[2 * p + 1]);
        }
#pragma unroll
        for (int p = 0; p < 8; p++) {
            ulonglong2 v = w1[p];
            hhA[2 * p]     = ffma2(x1bA, v.x, hhA[2 * p]);
            hhA[2 * p + 1] = ffma2(x1bA, v.y, hhA[2 * p + 1]);
            hhB[2 * p]     = ffma2(x1bB, v.x, hhB[2 * p]);
            hhB[2 * p + 1] = ffma2(x1bB, v.y, hhB[2 * p + 1]);
        }

        ull acc1A = pk2(fb[2], fb[3]), acc2A = pk2(fb[4], fb[5]);
        ull acc1B = acc1A, acc2B = acc2A;
#pragma unroll
        for (int j = 0; j < 16; j++) {
            float aA, bA, aB, bB;
            unpk2(hhA[j], aA, bA); unpk2(hhB[j], aB, bB);
            aA = fmaxf(aA, 0.f); bA = fmaxf(bA, 0.f);
            aB = fmaxf(aB, 0.f); bB = fmaxf(bB, 0.f);
            ull abA = pk2(aA, aA), bbA = pk2(bA, bA);
            ull abB = pk2(aB, aB), bbB = pk2(bB, bB);
            ull wv = reinterpret_cast<const ull*>(foA)[j];
            ulonglong2 wv2 = reinterpret_cast<const ulonglong2*>(foB)[j];
            acc1A = ffma2(abA, wv, acc1A);
            acc2A = ffma2(abA, wv2.x, acc2A);
            acc2A = ffma2(bbA, wv2.y, acc2A);
            acc1B = ffma2(abB, wv, acc1B);
            acc2B = ffma2(abB, wv2.x, acc2B);
            acc2B = ffma2(bbB, wv2.y, acc2B);
        }
        float bmu0 = fb[0], esc0 = fb[1];
        {
            float mu1, al1, mu2, al2;
            unpk2(acc1A, mu1, al1); unpk2(acc2A, mu2, al2);
            float t1 = 1.f - __fdividef(2.f, __expf(2.f * al1) + 1.f);
            float t2 = 1.f - __fdividef(2.f, __expf(2.f * al2) + 1.f);
            float nx0 = (x0A - bmu0) * esc0;
            float nx1 = (x1A - mu1) * __expf(-t1);
            float nx2 = (x2A - mu2) * __expf(-t2);
            x0A = nx2; x1A = nx1; x2A = nx0;
        }
        {
            float mu1, al1, mu2, al2;
            unpk2(acc1B, mu1, al1); unpk2(acc2B, mu2, al2);
            float t1 = 1.f - __fdividef(2.f, __expf(2.f * al1) + 1.f);
            float t2 = 1.f - __fdividef(2.f, __expf(2.f * al2) + 1.f);
            float nx0 = (x0B - bmu0) * esc0;
            float nx1 = (x1B - mu1) * __expf(-t1);
            float nx2 = (x2B - mu2) * __expf(-t2);
            x0B = nx2; x1B = nx1; x2B = nx0;
        }
    }

    // ---- squash + HSV + store ----
    if (v0) {
        float u0 = __fdividef(1.f, 1.f + __expf(-x0A));
        float u1 = __fdividef(1.f, 1.f + __expf(-x1A));
        float u2 = __fdividef(1.f, 1.f + __expf(-x2A));
        out[3 * r0 + 0] = 6.2831853071795864769f * u0;
        out[3 * r0 + 1] = u1;
        out[3 * r0 + 2] = u2;
    }
    if (v1) {
        float u0 = __fdividef(1.f, 1.f + __expf(-x0B));
        float u1 = __fdividef(1.f, 1.f + __expf(-x1B));
        float u2 = __fdividef(1.f, 1.f + __expf(-x2B));
        out[3 * r1 + 0] = 6.2831853071795864769f * u0;
        out[3 * r1 + 1] = u1;
        out[3 * r1 + 2] = u2;
    }
}

extern "C" void kernel_launch(void* const* d_in, const int* in_sizes, int n_in,
                              void* d_out, int out_size) {
    (void)n_in; (void)out_size;
    const float* states   = (const float*)d_in[0];
    const float* enc_w1   = (const float*)d_in[1];
    const float* enc_b1   = (const float*)d_in[2];
    const float* enc_w2   = (const float*)d_in[3];
    const float* enc_b2   = (const float*)d_in[4];
    const float* enc_w3   = (const float*)d_in[5];
    const float* enc_b3   = (const float*)d_in[6];
    const float* proj_w   = (const float*)d_in[7];
    const float* proj_b   = (const float*)d_in[8];
    const float* flow_wh  = (const float*)d_in[9];
    const float* flow_bh  = (const float*)d_in[10];
    const float* flow_wmu = (const float*)d_in[11];
    const float* flow_bmu = (const float*)d_in[12];
    const float* flow_wa  = (const float*)d_in[13];
    const float* flow_ba  = (const float*)d_in[14];

    const int B = in_sizes[0] / 4;
    const int grid = (B + 255) / 256;
    gsi_kernel<<<grid, 128>>>(states, enc_w1, enc_b1, enc_w2, enc_b2, enc_w3, enc_b3,
                              proj_w, proj_b, flow_wh, flow_bh, flow_wmu, flow_bmu,
                              flow_wa, flow_ba, (float*)d_out, B);
}